// round 15
// baseline (speedup 1.0000x reference)
#include <cuda_runtime.h>
#include <cuda_fp16.h>
#include <math.h>

#define BB 4
#define SS 2048
#define EE 512
#define HH 8
#define DD 64
#define QP 72                     // smem pitch in halves (144B, conflict-free ldmatrix)
#define LOG2E8 0.18033688011112042f   // log2(e)/8

// ---------------------------------------------------------------------------
// Scratch (__device__ globals; allocation-free rule)
// ---------------------------------------------------------------------------
__device__ __align__(16) __half g_xh [BB*SS*EE];      // x fp16
__device__ __align__(16) __half g_wqh[3*EE*EE];       // Wqkv_w fp16
__device__ __align__(16) __half g_woh[EE*EE];         // out_w fp16
__device__ __align__(16) __half g_qh [BB*HH*SS*DD];   // q * log2e/8
__device__ __align__(16) __half g_kh [BB*HH*SS*DD];
__device__ __align__(16) __half g_vh [BB*HH*SS*DD];
__device__ __align__(16) __half g_oh [BB*SS*EE];      // attn out, [b*s, h*d]
__device__ __align__(16) unsigned g_adjbits[BB*SS*(SS/32)];

// ---------------------------------------------------------------------------
// PTX helpers
// ---------------------------------------------------------------------------
__device__ __forceinline__ unsigned smem_u32(const void* p) {
    unsigned a;
    asm("{ .reg .u64 t; cvta.to.shared.u64 t, %1; cvt.u32.u64 %0, t; }"
        : "=r"(a) : "l"(p));
    return a;
}

__device__ __forceinline__ void ldm_x4(unsigned* r, unsigned addr) {
    asm volatile("ldmatrix.sync.aligned.m8n8.x4.shared.b16 {%0,%1,%2,%3}, [%4];"
                 : "=r"(r[0]), "=r"(r[1]), "=r"(r[2]), "=r"(r[3]) : "r"(addr));
}

__device__ __forceinline__ void ldm_x4_t(unsigned* r, unsigned addr) {
    asm volatile("ldmatrix.sync.aligned.m8n8.x4.trans.shared.b16 {%0,%1,%2,%3}, [%4];"
                 : "=r"(r[0]), "=r"(r[1]), "=r"(r[2]), "=r"(r[3]) : "r"(addr));
}

__device__ __forceinline__ void mma16816(float* c, const unsigned* a,
                                         const unsigned* b) {
    asm volatile(
        "mma.sync.aligned.m16n8k16.row.col.f32.f16.f16.f32 "
        "{%0,%1,%2,%3}, {%4,%5,%6,%7}, {%8,%9}, {%0,%1,%2,%3};"
        : "+f"(c[0]), "+f"(c[1]), "+f"(c[2]), "+f"(c[3])
        : "r"(a[0]), "r"(a[1]), "r"(a[2]), "r"(a[3]), "r"(b[0]), "r"(b[1]));
}

// fp16-accumulator variant: d = 2 packed-half2 regs
// d[0] = (row gid,   cols 2tig..2tig+1), d[1] = (row gid+8, same cols)
__device__ __forceinline__ void mma16816_h(unsigned* d, const unsigned* a,
                                           const unsigned* b) {
    asm volatile(
        "mma.sync.aligned.m16n8k16.row.col.f16.f16.f16.f16 "
        "{%0,%1}, {%2,%3,%4,%5}, {%6,%7}, {%0,%1};"
        : "+r"(d[0]), "+r"(d[1])
        : "r"(a[0]), "r"(a[1]), "r"(a[2]), "r"(a[3]), "r"(b[0]), "r"(b[1]));
}

__device__ __forceinline__ unsigned h2_exp2u(unsigned xi) {
    unsigned ri;
    asm("ex2.approx.f16x2 %0, %1;" : "=r"(ri) : "r"(xi));
    return ri;
}

#define CP_ASYNC(d, s) asm volatile("cp.async.cg.shared.global [%0], [%1], 16;" :: "r"(d), "l"(s))
#define CP_COMMIT()    asm volatile("cp.async.commit_group;")
#define CP_WAIT1()     asm volatile("cp.async.wait_group 1;")
#define CP_WAIT0()     asm volatile("cp.async.wait_group 0;")

// ---------------------------------------------------------------------------
// Kernel A: fp32 -> fp16 conversion for x and Wqkv_w (grid 2432)
// ---------------------------------------------------------------------------
__global__ __launch_bounds__(256) void conv_kernel(
    const float* __restrict__ x, const float* __restrict__ wq)
{
    int idx = blockIdx.x * 256 + threadIdx.x;
    const float* src;
    __half* dst;
    if (idx < 524288) { src = x  + (size_t)idx * 8;             dst = g_xh  + (size_t)idx * 8; }
    else              { src = wq + ((size_t)idx - 524288) * 8;  dst = g_wqh + ((size_t)idx - 524288) * 8; }
    float4 f0 = *(const float4*)src;
    float4 f1 = *(const float4*)(src + 4);
    __half2 h[4] = {__floats2half2_rn(f0.x, f0.y), __floats2half2_rn(f0.z, f0.w),
                    __floats2half2_rn(f1.x, f1.y), __floats2half2_rn(f1.z, f1.w)};
    *(uint4*)dst = *(uint4*)h;
}

// ---------------------------------------------------------------------------
// Kernel C: fused QKV projection + adj bitmask pack + out_w conversion
// (R13 structure; GEMM role 4m x 2n).
// ---------------------------------------------------------------------------
__global__ __launch_bounds__(256, 2) void qkvpack_kernel(
    const float* __restrict__ bias, const float* __restrict__ adj,
    const float* __restrict__ wo)
{
    // ---- out_w conversion role ----
    if (blockIdx.x >= 2048) {
        int idx = (blockIdx.x - 2048) * 256 + threadIdx.x;   // 0..32767
        const float* src = wo + (size_t)idx * 8;
        __half* dst = g_woh + (size_t)idx * 8;
        float4 f0 = *(const float4*)src;
        float4 f1 = *(const float4*)(src + 4);
        __half2 h[4] = {__floats2half2_rn(f0.x, f0.y), __floats2half2_rn(f0.z, f0.w),
                        __floats2half2_rn(f1.x, f1.y), __floats2half2_rn(f1.z, f1.w)};
        *(uint4*)dst = *(uint4*)h;
        return;
    }

    // ---- adj pack role ----
    if ((blockIdx.x & 3) == 3) {
        const int p = blockIdx.x >> 2;             // 0..511
        const int wid = threadIdx.x >> 5, lane = threadIdx.x & 31;
        const float* basef = adj + ((size_t)p * 1024 + wid * 128) * 32;
        unsigned* outw = g_adjbits + p * 1024 + wid * 128;
        #pragma unroll 4
        for (int s = 0; s < 32; s++) {
            const float* src = basef + (size_t)s * 128;
            float v0 = src[lane];
            float v1 = src[lane + 32];
            float v2 = src[lane + 64];
            float v3 = src[lane + 96];
            unsigned w0 = __ballot_sync(0xffffffffu, v0 != 0.0f);
            unsigned w1 = __ballot_sync(0xffffffffu, v1 != 0.0f);
            unsigned w2 = __ballot_sync(0xffffffffu, v2 != 0.0f);
            unsigned w3 = __ballot_sync(0xffffffffu, v3 != 0.0f);
            if (lane == 0) {
                uint4 w = make_uint4(w0, w1, w2, w3);
                *(uint4*)(outw + s * 4) = w;
            }
        }
        return;
    }

    // ---- GEMM role (4m x 2n warp grid) ----
    const int g = (blockIdx.x >> 2) * 3 + (blockIdx.x & 3);   // 0..1535
    const int m0 = (g / 24) * 128, n0 = (g % 24) * 64;

    extern __shared__ __align__(16) __half sm[];
    const unsigned sAb = smem_u32(sm);
    const unsigned sBb = sAb + 55296;

    const int tid = threadIdx.x;
    const int wid = tid >> 5, lane = tid & 31;
    const int gid = lane >> 2, tig = lane & 3, lr = lane & 7;
    const int mw = wid & 3, nw = wid >> 2;

    const __half* A = g_xh;    // [8192,512]
    const __half* B = g_wqh;   // [1536,512]
    const int ar = tid >> 3, ac = tid & 7;

    #define QKV_ISSUE(kc, st) do { \
        unsigned da = sAb + (st) * 18432; \
        const __half* as = A + (size_t)(m0 + ar) * 512 + (kc) * 64 + ac * 8; \
        CP_ASYNC(da + (ar * QP + ac * 8) * 2, as); \
        CP_ASYNC(da + ((ar + 32) * QP + ac * 8) * 2, as + 32 * 512); \
        CP_ASYNC(da + ((ar + 64) * QP + ac * 8) * 2, as + 64 * 512); \
        CP_ASYNC(da + ((ar + 96) * QP + ac * 8) * 2, as + 96 * 512); \
        unsigned db = sBb + (st) * 9216; \
        const __half* bs = B + (size_t)(n0 + ar) * 512 + (kc) * 64 + ac * 8; \
        CP_ASYNC(db + (ar * QP + ac * 8) * 2, bs); \
        CP_ASYNC(db + ((ar + 32) * QP + ac * 8) * 2, bs + 32 * 512); \
    } while (0)

    const unsigned aq0 = ((mw * 32 + (lane & 15)) * QP + (lane >> 4) * 8) * 2;
    const unsigned aq1 = ((mw * 32 + 16 + (lane & 15)) * QP + (lane >> 4) * 8) * 2;
    const unsigned bq  = (((lane >> 4) * 8 + lr) * QP + ((lane >> 3) & 1) * 8) * 2;

    float c[2][4][4] = {};

    QKV_ISSUE(0, 0); CP_COMMIT();
    QKV_ISSUE(1, 1); CP_COMMIT();

    int st = 0, sti = 2;
    for (int kc = 0; kc < 8; kc++) {
        if (kc == 7) CP_WAIT0(); else CP_WAIT1();
        __syncthreads();
        if (kc < 6) { QKV_ISSUE(kc + 2, sti); CP_COMMIT(); }
        const unsigned ab = sAb + st * 18432;
        const unsigned bb = sBb + st * 9216;
        #pragma unroll
        for (int s = 0; s < 4; s++) {
            unsigned af0[4], af1[4];
            ldm_x4(af0, ab + aq0 + s * 32);
            ldm_x4(af1, ab + aq1 + s * 32);
            #pragma unroll
            for (int p = 0; p < 2; p++) {
                unsigned bf[4];
                ldm_x4(bf, bb + bq + (nw * 2 + p) * (16 * QP * 2) + s * 32);
                mma16816(c[0][2 * p],     af0, bf);
                mma16816(c[0][2 * p + 1], af0, bf + 2);
                mma16816(c[1][2 * p],     af1, bf);
                mma16816(c[1][2 * p + 1], af1, bf + 2);
            }
        }
        st = (st == 2) ? 0 : st + 1;
        sti = (sti == 2) ? 0 : sti + 1;
    }

    #pragma unroll
    for (int rt = 0; rt < 2; rt++) {
        const int r0 = m0 + mw * 32 + rt * 16 + gid;
        const int bi0 = r0 >> 11, si0 = r0 & 2047;
        const int r1 = r0 + 8;
        const int bi1 = r1 >> 11, si1 = r1 & 2047;
        #pragma unroll
        for (int nt = 0; nt < 4; nt++) {
            int col = n0 + nw * 32 + nt * 8 + 2 * tig;
            float b0 = bias[col], b1 = bias[col + 1];
            int t = col >> 9, rem = col & 511;
            int hh = rem >> 6, di = rem & 63;
            float sc = (t == 0) ? LOG2E8 : 1.0f;
            __half2 h0 = __floats2half2_rn((c[rt][nt][0] + b0) * sc, (c[rt][nt][1] + b1) * sc);
            __half2 h1 = __floats2half2_rn((c[rt][nt][2] + b0) * sc, (c[rt][nt][3] + b1) * sc);
            size_t d0 = (((size_t)(bi0 * HH + hh) * SS) + si0) * DD + di;
            size_t d1 = (((size_t)(bi1 * HH + hh) * SS) + si1) * DD + di;
            __half* base = (t == 0) ? g_qh : (t == 1) ? g_kh : g_vh;
            *(__half2*)(base + d0) = h0;
            *(__half2*)(base + d1) = h1;
        }
    }
}

// ---------------------------------------------------------------------------
// Kernel D: HMMA flash attention — R14 kernel at 3 CTAs/SM.
// fp16-accumulator S-MMA halves S register footprint (su 32 u32 vs 64 fp32),
// fitting the 170-reg budget of launch_bounds(128,3): 12 warps/SM and
// grid 512 / 444 concurrent = 1.15 waves (vs 1.73 at occ 2).
// Smem: Q 18432 + K 3x9216 + V 3x9216 = 73728 B; 3 CTAs = 221 KB/SM.
// ---------------------------------------------------------------------------
__global__ __launch_bounds__(128, 3) void attn_kernel()
{
    extern __shared__ __align__(16) __half sm[];
    const unsigned sQb = smem_u32(sm);
    const unsigned sKb = sQb + 18432;   // + st*9216
    const unsigned sVb = sQb + 46080;   // + st*9216

    const int tid = threadIdx.x;
    const int wid = tid >> 5, lane = tid & 31;
    const int gid = lane >> 2, tig = lane & 3, lr = lane & 7;

    const int q0 = blockIdx.x * 128;
    const int hi = blockIdx.y, bi = blockIdx.z;
    const int bh = bi * HH + hi;

    const __half* Qg = g_qh + (size_t)bh * SS * DD;
    const __half* Kg = g_kh + (size_t)bh * SS * DD;
    const __half* Vg = g_vh + (size_t)bh * SS * DD;

    const int kr = tid >> 3, kc8 = tid & 7;   // 16 rows per pass, 4 passes

    #define KV_ISSUE(kt, st) do { \
        const __half* ks = Kg + (size_t)((kt) * 64 + kr) * DD + kc8 * 8; \
        const __half* vs = Vg + (size_t)((kt) * 64 + kr) * DD + kc8 * 8; \
        unsigned dk = sKb + (st) * 9216 + (kr * QP + kc8 * 8) * 2; \
        unsigned dv = sVb + (st) * 9216 + (kr * QP + kc8 * 8) * 2; \
        CP_ASYNC(dk, ks); \
        CP_ASYNC(dk + 16 * QP * 2, ks + 16 * DD); \
        CP_ASYNC(dk + 32 * QP * 2, ks + 32 * DD); \
        CP_ASYNC(dk + 48 * QP * 2, ks + 48 * DD); \
        CP_ASYNC(dv, vs); \
        CP_ASYNC(dv + 16 * QP * 2, vs + 16 * DD); \
        CP_ASYNC(dv + 32 * QP * 2, vs + 32 * DD); \
        CP_ASYNC(dv + 48 * QP * 2, vs + 48 * DD); \
    } while (0)

    // Q tile: 128 rows (plain stores)
    {
        const uint4* src = (const uint4*)(Qg + (size_t)q0 * DD);
        #pragma unroll
        for (int i = tid; i < 1024; i += 128) {
            int r = i >> 3, cc = i & 7;
            *(uint4*)(sm + r * QP + cc * 8) = src[r * 8 + cc];
        }
    }

    KV_ISSUE(0, 0); CP_COMMIT();
    KV_ISSUE(1, 1); CP_COMMIT();
    __syncthreads();   // covers Q stores

    // Q a-frags: 2 row-tiles x 4 k-steps
    unsigned qa[2][4][4];
    #pragma unroll
    for (int rt = 0; rt < 2; rt++) {
        int qrow = wid * 32 + rt * 16 + (lane & 15);
        int cofs = (lane >> 4) * 8;
        #pragma unroll
        for (int s = 0; s < 4; s++)
            ldm_x4(qa[rt][s], sQb + (qrow * QP + s * 16 + cofs) * 2);
    }

    const unsigned kq = (((lane >> 4) * 8 + lr) * QP + ((lane >> 3) & 1) * 8) * 2;
    const unsigned vq = ((((lane >> 3) & 1) * 8 + lr) * QP + (lane >> 4) * 8) * 2;

    // adjacency row pointers: 2 row-tiles x 2 subrows
    const unsigned* mp00 = g_adjbits + ((size_t)bi * SS + q0 + wid * 32 + gid) * (SS / 32);
    const unsigned* mp01 = mp00 + 8  * (SS / 32);
    const unsigned* mp10 = mp00 + 16 * (SS / 32);
    const unsigned* mp11 = mp00 + 24 * (SS / 32);

    const unsigned onesb[2] = {0x3C003C00u, 0x3C003C00u};  // fp16 {1,1}

    float oc[2][8][4] = {};
    float cl[2][4] = {};

    int st = 0, sti = 2;
    for (int kt = 0; kt < 32; kt++) {
        if (kt == 31) CP_WAIT0(); else CP_WAIT1();
        __syncthreads();
        if (kt < 30) { KV_ISSUE(kt + 2, sti); CP_COMMIT(); }

        const unsigned kb_base = sKb + st * 9216;
        const unsigned vb_base = sVb + st * 9216;

        // S(log2-domain) = Qs . K^T, fp16 accumulator
        unsigned su[2][8][2] = {};
        #pragma unroll
        for (int s = 0; s < 4; s++) {
            #pragma unroll
            for (int ntp = 0; ntp < 4; ntp++) {
                unsigned kb[4];
                ldm_x4(kb, kb_base + kq + ntp * (16 * QP * 2) + s * 32);
                mma16816_h(su[0][2 * ntp],     qa[0][s], kb);
                mma16816_h(su[0][2 * ntp + 1], qa[0][s], kb + 2);
                mma16816_h(su[1][2 * ntp],     qa[1][s], kb);
                mma16816_h(su[1][2 * ntp + 1], qa[1][s], kb + 2);
            }
        }

        // masked 2^s epilogue: AND + ex2 directly on packed f16 d-frags
        unsigned ph[2][8][2];
        #pragma unroll
        for (int rt = 0; rt < 2; rt++) {
            const uint2 wv0 = *(const uint2*)((rt ? mp10 : mp00) + 2 * kt);
            const uint2 wv1 = *(const uint2*)((rt ? mp11 : mp01) + 2 * kt);
            #pragma unroll
            for (int nt = 0; nt < 8; nt++) {
                int cb = nt * 8 + 2 * tig;
                unsigned wa = (cb < 32) ? wv0.x : wv0.y;
                unsigned wb = (cb < 32) ? wv1.x : wv1.y;
                int sh = cb & 31;
                unsigned ba  = (wa >> sh) & 3u;
                unsigned bb2 = (wb >> sh) & 3u;
                unsigned mA = ((ba & 1u) ? 0x0000FFFFu : 0u) | ((ba & 2u) ? 0xFFFF0000u : 0u);
                unsigned mB = ((bb2 & 1u) ? 0x0000FFFFu : 0u) | ((bb2 & 2u) ? 0xFFFF0000u : 0u);
                ph[rt][nt][0] = h2_exp2u(su[rt][nt][0] & mA);
                ph[rt][nt][1] = h2_exp2u(su[rt][nt][1] & mB);
            }
        }

        // O += P . V ; l += P . 1  — each vb ldm feeds 4 MMAs
        #pragma unroll
        for (int s = 0; s < 4; s++) {
            unsigned pa0[4] = {ph[0][2 * s][0], ph[0][2 * s][1],
                               ph[0][2 * s + 1][0], ph[0][2 * s + 1][1]};
            unsigned pa1[4] = {ph[1][2 * s][0], ph[1][2 * s][1],
                               ph[1][2 * s + 1][0], ph[1][2 * s + 1][1]};
            mma16816(cl[0], pa0, onesb);
            mma16816(cl[1], pa1, onesb);
            #pragma unroll
            for (int ntp = 0; ntp < 4; ntp++) {
                unsigned vb[4];
                ldm_x4_t(vb, vb_base + vq + s * (16 * QP * 2) + ntp * 32);
                mma16816(oc[0][2 * ntp],     pa0, vb);
                mma16816(oc[0][2 * ntp + 1], pa0, vb + 2);
                mma16816(oc[1][2 * ntp],     pa1, vb);
                mma16816(oc[1][2 * ntp + 1], pa1, vb + 2);
            }
        }

        st = (st == 2) ? 0 : st + 1;
        sti = (sti == 2) ? 0 : sti + 1;
    }

    // store (no reduction: each warp owns its 32 rows completely)
    #pragma unroll
    for (int rt = 0; rt < 2; rt++) {
        const float inv0 = 1.0f / cl[rt][0], inv1 = 1.0f / cl[rt][2];
        const int r = q0 + wid * 32 + rt * 16 + gid;
        __half* o0 = g_oh + ((size_t)bi * SS + r) * EE + hi * 64;
        __half* o1 = o0 + 8 * EE;
        #pragma unroll
        for (int nt = 0; nt < 8; nt++) {
            int cc = nt * 8 + 2 * tig;
            *(__half2*)(o0 + cc) = __floats2half2_rn(oc[rt][nt][0] * inv0,
                                                     oc[rt][nt][1] * inv0);
            *(__half2*)(o1 + cc) = __floats2half2_rn(oc[rt][nt][2] * inv1,
                                                     oc[rt][nt][3] * inv1);
        }
    }
}

// ---------------------------------------------------------------------------
// Kernel E: output projection, HMMA (R9-R14 version, measured ~21us).
// ---------------------------------------------------------------------------
__global__ __launch_bounds__(128, 4) void out_hmma_kernel(
    const float* __restrict__ bias, float* __restrict__ out)
{
    extern __shared__ __align__(16) __half sm[];
    const unsigned sAb = smem_u32(sm);            // 3 stages x 9216
    const unsigned sBb = sAb + 27648;             // 3 stages x 9216

    const int tid = threadIdx.x;
    const int wid = tid >> 5, lane = tid & 31;
    const int gid = lane >> 2, tig = lane & 3, lr = lane & 7;
    const int m0 = blockIdx.y * 64, n0 = blockIdx.x * 64;

    const __half* A = g_oh;    // [8192,512]
    const __half* B = g_woh;   // [512,512]
    const int ar = tid >> 3, ac = tid & 7;        // 16 rows per pass

    #define OUT_ISSUE(kc, st) do { \
        unsigned da = sAb + (st) * 9216; \
        const __half* as = A + (size_t)(m0 + ar) * 512 + (kc) * 64 + ac * 8; \
        CP_ASYNC(da + (ar * QP + ac * 8) * 2, as); \
        CP_ASYNC(da + ((ar + 16) * QP + ac * 8) * 2, as + 16 * 512); \
        CP_ASYNC(da + ((ar + 32) * QP + ac * 8) * 2, as + 32 * 512); \
        CP_ASYNC(da + ((ar + 48) * QP + ac * 8) * 2, as + 48 * 512); \
        unsigned db = sBb + (st) * 9216; \
        const __half* bs = B + (size_t)(n0 + ar) * 512 + (kc) * 64 + ac * 8; \
        CP_ASYNC(db + (ar * QP + ac * 8) * 2, bs); \
        CP_ASYNC(db + ((ar + 16) * QP + ac * 8) * 2, bs + 16 * 512); \
        CP_ASYNC(db + ((ar + 32) * QP + ac * 8) * 2, bs + 32 * 512); \
        CP_ASYNC(db + ((ar + 48) * QP + ac * 8) * 2, bs + 48 * 512); \
    } while (0)

    const unsigned aq = ((wid * 16 + (lane & 15)) * QP + (lane >> 4) * 8) * 2;
    const unsigned bq = (((lane >> 4) * 8 + lr) * QP + ((lane >> 3) & 1) * 8) * 2;

    float c[8][4] = {};

    OUT_ISSUE(0, 0); CP_COMMIT();
    OUT_ISSUE(1, 1); CP_COMMIT();

    int st = 0, sti = 2;
    for (int kc = 0; kc < 8; kc++) {
        if (kc == 7) CP_WAIT0(); else CP_WAIT1();
        __syncthreads();
        if (kc < 6) { OUT_ISSUE(kc + 2, sti); CP_COMMIT(); }
        const unsigned ab = sAb + st * 9216;
        const unsigned bb = sBb + st * 9216;
        #pragma unroll
        for (int s = 0; s < 4; s++) {
            unsigned af[4];
            ldm_x4(af, ab + aq + s * 32);
            #pragma unroll
            for (int ntp = 0; ntp < 4; ntp++) {
                unsigned bf[4];
                ldm_x4(bf, bb + bq + ntp * (16 * QP * 2) + s * 32);
                mma16816(c[2 * ntp],     af, bf);
                mma16816(c[2 * ntp + 1], af, bf + 2);
            }
        }
        st = (st == 2) ? 0 : st + 1;
        sti = (sti == 2) ? 0 : sti + 1;
    }

    const int r0 = m0 + wid * 16 + gid;
    float* o0 = out + (size_t)r0 * EE;
    float* o1 = o0 + 8 * EE;
    #pragma unroll
    for (int nt = 0; nt < 8; nt++) {
        int col = n0 + nt * 8 + 2 * tig;
        float b0 = bias[col], b1 = bias[col + 1];
        *(float2*)(o0 + col) = make_float2(c[nt][0] + b0, c[nt][1] + b1);
        *(float2*)(o1 + col) = make_float2(c[nt][2] + b0, c[nt][3] + b1);
    }
}

// ---------------------------------------------------------------------------
// Launch
// ---------------------------------------------------------------------------
extern "C" void kernel_launch(void* const* d_in, const int* in_sizes, int n_in,
                              void* d_out, int out_size)
{
    const float* x      = (const float*)d_in[0];
    const float* adj    = (const float*)d_in[1];
    const float* Wqkv_w = (const float*)d_in[2];
    const float* Wqkv_b = (const float*)d_in[3];
    const float* out_w  = (const float*)d_in[4];
    const float* out_b  = (const float*)d_in[5];
    float* out = (float*)d_out;

    cudaFuncSetAttribute(qkvpack_kernel,  cudaFuncAttributeMaxDynamicSharedMemorySize, 82944);
    cudaFuncSetAttribute(attn_kernel,     cudaFuncAttributeMaxDynamicSharedMemorySize, 73728);
    cudaFuncSetAttribute(out_hmma_kernel, cudaFuncAttributeMaxDynamicSharedMemorySize, 55296);

    conv_kernel<<<2432, 256>>>(x, Wqkv_w);
    qkvpack_kernel<<<2176, 256, 82944>>>(Wqkv_b, adj, out_w);
    attn_kernel<<<dim3(SS / 128, HH, BB), 128, 73728>>>();
    out_hmma_kernel<<<dim3(8, 128), 128, 55296>>>(out_b, out);
}

// round 16
// speedup vs baseline: 1.1618x; 1.1618x over previous
#include <cuda_runtime.h>
#include <cuda_fp16.h>
#include <math.h>

#define BB 4
#define SS 2048
#define EE 512
#define HH 8
#define DD 64
#define QP 72                     // smem pitch in halves (144B, conflict-free ldmatrix)
#define LOG2E8 0.18033688011112042f   // log2(e)/8

// ---------------------------------------------------------------------------
// Scratch (__device__ globals; allocation-free rule)
// ---------------------------------------------------------------------------
__device__ __align__(16) __half g_xh [BB*SS*EE];      // x fp16
__device__ __align__(16) __half g_wqh[3*EE*EE];       // Wqkv_w fp16
__device__ __align__(16) __half g_woh[EE*EE];         // out_w fp16
__device__ __align__(16) __half g_qh [BB*HH*SS*DD];   // q * log2e/8
__device__ __align__(16) __half g_kh [BB*HH*SS*DD];
__device__ __align__(16) __half g_vh [BB*HH*SS*DD];
__device__ __align__(16) __half g_oh [BB*SS*EE];      // attn out, [b*s, h*d]
__device__ __align__(16) unsigned g_adjbits[BB*SS*(SS/32)];

// ---------------------------------------------------------------------------
// PTX helpers
// ---------------------------------------------------------------------------
__device__ __forceinline__ unsigned smem_u32(const void* p) {
    unsigned a;
    asm("{ .reg .u64 t; cvta.to.shared.u64 t, %1; cvt.u32.u64 %0, t; }"
        : "=r"(a) : "l"(p));
    return a;
}

__device__ __forceinline__ void ldm_x4(unsigned* r, unsigned addr) {
    asm volatile("ldmatrix.sync.aligned.m8n8.x4.shared.b16 {%0,%1,%2,%3}, [%4];"
                 : "=r"(r[0]), "=r"(r[1]), "=r"(r[2]), "=r"(r[3]) : "r"(addr));
}

__device__ __forceinline__ void ldm_x4_t(unsigned* r, unsigned addr) {
    asm volatile("ldmatrix.sync.aligned.m8n8.x4.trans.shared.b16 {%0,%1,%2,%3}, [%4];"
                 : "=r"(r[0]), "=r"(r[1]), "=r"(r[2]), "=r"(r[3]) : "r"(addr));
}

__device__ __forceinline__ void mma16816(float* c, const unsigned* a,
                                         const unsigned* b) {
    asm volatile(
        "mma.sync.aligned.m16n8k16.row.col.f32.f16.f16.f32 "
        "{%0,%1,%2,%3}, {%4,%5,%6,%7}, {%8,%9}, {%0,%1,%2,%3};"
        : "+f"(c[0]), "+f"(c[1]), "+f"(c[2]), "+f"(c[3])
        : "r"(a[0]), "r"(a[1]), "r"(a[2]), "r"(a[3]), "r"(b[0]), "r"(b[1]));
}

// fp16-accumulator variant: d = 2 packed-half2 regs
// d[0] = (row gid,   cols 2tig..2tig+1), d[1] = (row gid+8, same cols)
__device__ __forceinline__ void mma16816_h(unsigned* d, const unsigned* a,
                                           const unsigned* b) {
    asm volatile(
        "mma.sync.aligned.m16n8k16.row.col.f16.f16.f16.f16 "
        "{%0,%1}, {%2,%3,%4,%5}, {%6,%7}, {%0,%1};"
        : "+r"(d[0]), "+r"(d[1])
        : "r"(a[0]), "r"(a[1]), "r"(a[2]), "r"(a[3]), "r"(b[0]), "r"(b[1]));
}

__device__ __forceinline__ unsigned h2_exp2u(unsigned xi) {
    unsigned ri;
    asm("ex2.approx.f16x2 %0, %1;" : "=r"(ri) : "r"(xi));
    return ri;
}

#define CP_ASYNC(d, s) asm volatile("cp.async.cg.shared.global [%0], [%1], 16;" :: "r"(d), "l"(s))
#define CP_COMMIT()    asm volatile("cp.async.commit_group;")
#define CP_WAIT2()     asm volatile("cp.async.wait_group 2;")
#define CP_WAIT1()     asm volatile("cp.async.wait_group 1;")
#define CP_WAIT0()     asm volatile("cp.async.wait_group 0;")

// ---------------------------------------------------------------------------
// Kernel A: fp32 -> fp16 conversion for x and Wqkv_w (grid 2432)
// ---------------------------------------------------------------------------
__global__ __launch_bounds__(256) void conv_kernel(
    const float* __restrict__ x, const float* __restrict__ wq)
{
    int idx = blockIdx.x * 256 + threadIdx.x;
    const float* src;
    __half* dst;
    if (idx < 524288) { src = x  + (size_t)idx * 8;             dst = g_xh  + (size_t)idx * 8; }
    else              { src = wq + ((size_t)idx - 524288) * 8;  dst = g_wqh + ((size_t)idx - 524288) * 8; }
    float4 f0 = *(const float4*)src;
    float4 f1 = *(const float4*)(src + 4);
    __half2 h[4] = {__floats2half2_rn(f0.x, f0.y), __floats2half2_rn(f0.z, f0.w),
                    __floats2half2_rn(f1.x, f1.y), __floats2half2_rn(f1.z, f1.w)};
    *(uint4*)dst = *(uint4*)h;
}

// ---------------------------------------------------------------------------
// Kernel C: fused QKV projection + adj bitmask pack + out_w conversion.
// GEMM role now 4-stage cp.async (deeper prefetch margin against the DRAM
// bandwidth contention from pack CTAs). Smem 110592 B, 2 CTAs/SM = 221 KB.
// ---------------------------------------------------------------------------
__global__ __launch_bounds__(256, 2) void qkvpack_kernel(
    const float* __restrict__ bias, const float* __restrict__ adj,
    const float* __restrict__ wo)
{
    // ---- out_w conversion role ----
    if (blockIdx.x >= 2048) {
        int idx = (blockIdx.x - 2048) * 256 + threadIdx.x;   // 0..32767
        const float* src = wo + (size_t)idx * 8;
        __half* dst = g_woh + (size_t)idx * 8;
        float4 f0 = *(const float4*)src;
        float4 f1 = *(const float4*)(src + 4);
        __half2 h[4] = {__floats2half2_rn(f0.x, f0.y), __floats2half2_rn(f0.z, f0.w),
                        __floats2half2_rn(f1.x, f1.y), __floats2half2_rn(f1.z, f1.w)};
        *(uint4*)dst = *(uint4*)h;
        return;
    }

    // ---- adj pack role ----
    if ((blockIdx.x & 3) == 3) {
        const int p = blockIdx.x >> 2;             // 0..511
        const int wid = threadIdx.x >> 5, lane = threadIdx.x & 31;
        const float* basef = adj + ((size_t)p * 1024 + wid * 128) * 32;
        unsigned* outw = g_adjbits + p * 1024 + wid * 128;
        #pragma unroll 4
        for (int s = 0; s < 32; s++) {
            const float* src = basef + (size_t)s * 128;
            float v0 = src[lane];
            float v1 = src[lane + 32];
            float v2 = src[lane + 64];
            float v3 = src[lane + 96];
            unsigned w0 = __ballot_sync(0xffffffffu, v0 != 0.0f);
            unsigned w1 = __ballot_sync(0xffffffffu, v1 != 0.0f);
            unsigned w2 = __ballot_sync(0xffffffffu, v2 != 0.0f);
            unsigned w3 = __ballot_sync(0xffffffffu, v3 != 0.0f);
            if (lane == 0) {
                uint4 w = make_uint4(w0, w1, w2, w3);
                *(uint4*)(outw + s * 4) = w;
            }
        }
        return;
    }

    // ---- GEMM role (4m x 2n warp grid, 4-stage pipeline) ----
    const int g = (blockIdx.x >> 2) * 3 + (blockIdx.x & 3);   // 0..1535
    const int m0 = (g / 24) * 128, n0 = (g % 24) * 64;

    extern __shared__ __align__(16) __half sm[];
    const unsigned sAb = smem_u32(sm);            // 4 stages x 18432
    const unsigned sBb = sAb + 73728;             // 4 stages x 9216

    const int tid = threadIdx.x;
    const int wid = tid >> 5, lane = tid & 31;
    const int gid = lane >> 2, tig = lane & 3, lr = lane & 7;
    const int mw = wid & 3, nw = wid >> 2;

    const __half* A = g_xh;    // [8192,512]
    const __half* B = g_wqh;   // [1536,512]
    const int ar = tid >> 3, ac = tid & 7;

    #define QKV_ISSUE(kc, st) do { \
        unsigned da = sAb + (st) * 18432; \
        const __half* as = A + (size_t)(m0 + ar) * 512 + (kc) * 64 + ac * 8; \
        CP_ASYNC(da + (ar * QP + ac * 8) * 2, as); \
        CP_ASYNC(da + ((ar + 32) * QP + ac * 8) * 2, as + 32 * 512); \
        CP_ASYNC(da + ((ar + 64) * QP + ac * 8) * 2, as + 64 * 512); \
        CP_ASYNC(da + ((ar + 96) * QP + ac * 8) * 2, as + 96 * 512); \
        unsigned db = sBb + (st) * 9216; \
        const __half* bs = B + (size_t)(n0 + ar) * 512 + (kc) * 64 + ac * 8; \
        CP_ASYNC(db + (ar * QP + ac * 8) * 2, bs); \
        CP_ASYNC(db + ((ar + 32) * QP + ac * 8) * 2, bs + 32 * 512); \
    } while (0)

    const unsigned aq0 = ((mw * 32 + (lane & 15)) * QP + (lane >> 4) * 8) * 2;
    const unsigned aq1 = ((mw * 32 + 16 + (lane & 15)) * QP + (lane >> 4) * 8) * 2;
    const unsigned bq  = (((lane >> 4) * 8 + lr) * QP + ((lane >> 3) & 1) * 8) * 2;

    float c[2][4][4] = {};

    QKV_ISSUE(0, 0); CP_COMMIT();
    QKV_ISSUE(1, 1); CP_COMMIT();
    QKV_ISSUE(2, 2); CP_COMMIT();

    int st = 0, sti = 3;
    for (int kc = 0; kc < 8; kc++) {
        if (kc == 7) CP_WAIT0(); else if (kc == 6) CP_WAIT1(); else CP_WAIT2();
        __syncthreads();
        if (kc < 5) { QKV_ISSUE(kc + 3, sti); CP_COMMIT(); }
        const unsigned ab = sAb + st * 18432;
        const unsigned bb = sBb + st * 9216;
        #pragma unroll
        for (int s = 0; s < 4; s++) {
            unsigned af0[4], af1[4];
            ldm_x4(af0, ab + aq0 + s * 32);
            ldm_x4(af1, ab + aq1 + s * 32);
            #pragma unroll
            for (int p = 0; p < 2; p++) {
                unsigned bf[4];
                ldm_x4(bf, bb + bq + (nw * 2 + p) * (16 * QP * 2) + s * 32);
                mma16816(c[0][2 * p],     af0, bf);
                mma16816(c[0][2 * p + 1], af0, bf + 2);
                mma16816(c[1][2 * p],     af1, bf);
                mma16816(c[1][2 * p + 1], af1, bf + 2);
            }
        }
        st = (st + 1) & 3;
        sti = (sti + 1) & 3;
    }

    #pragma unroll
    for (int rt = 0; rt < 2; rt++) {
        const int r0 = m0 + mw * 32 + rt * 16 + gid;
        const int bi0 = r0 >> 11, si0 = r0 & 2047;
        const int r1 = r0 + 8;
        const int bi1 = r1 >> 11, si1 = r1 & 2047;
        #pragma unroll
        for (int nt = 0; nt < 4; nt++) {
            int col = n0 + nw * 32 + nt * 8 + 2 * tig;
            float b0 = bias[col], b1 = bias[col + 1];
            int t = col >> 9, rem = col & 511;
            int hh = rem >> 6, di = rem & 63;
            float sc = (t == 0) ? LOG2E8 : 1.0f;
            __half2 h0 = __floats2half2_rn((c[rt][nt][0] + b0) * sc, (c[rt][nt][1] + b1) * sc);
            __half2 h1 = __floats2half2_rn((c[rt][nt][2] + b0) * sc, (c[rt][nt][3] + b1) * sc);
            size_t d0 = (((size_t)(bi0 * HH + hh) * SS) + si0) * DD + di;
            size_t d1 = (((size_t)(bi1 * HH + hh) * SS) + si1) * DD + di;
            __half* base = (t == 0) ? g_qh : (t == 1) ? g_kh : g_vh;
            *(__half2*)(base + d0) = h0;
            *(__half2*)(base + d1) = h1;
        }
    }
}

// ---------------------------------------------------------------------------
// Kernel D: HMMA flash attention — EXACT R14 kernel (best measured: ~120us).
// fp16-accumulator S-MMA, 128 threads / 4 warps, 32 q-rows/warp, 2 CTAs/SM.
// Smem: Q 18432 + K 3x9216 + V 3x9216 = 73728 B.
// ---------------------------------------------------------------------------
__global__ __launch_bounds__(128, 2) void attn_kernel()
{
    extern __shared__ __align__(16) __half sm[];
    const unsigned sQb = smem_u32(sm);
    const unsigned sKb = sQb + 18432;   // + st*9216
    const unsigned sVb = sQb + 46080;   // + st*9216

    const int tid = threadIdx.x;
    const int wid = tid >> 5, lane = tid & 31;
    const int gid = lane >> 2, tig = lane & 3, lr = lane & 7;

    const int q0 = blockIdx.x * 128;
    const int hi = blockIdx.y, bi = blockIdx.z;
    const int bh = bi * HH + hi;

    const __half* Qg = g_qh + (size_t)bh * SS * DD;
    const __half* Kg = g_kh + (size_t)bh * SS * DD;
    const __half* Vg = g_vh + (size_t)bh * SS * DD;

    const int kr = tid >> 3, kc8 = tid & 7;   // 16 rows per pass, 4 passes

    #define KV_ISSUE(kt, st) do { \
        const __half* ks = Kg + (size_t)((kt) * 64 + kr) * DD + kc8 * 8; \
        const __half* vs = Vg + (size_t)((kt) * 64 + kr) * DD + kc8 * 8; \
        unsigned dk = sKb + (st) * 9216 + (kr * QP + kc8 * 8) * 2; \
        unsigned dv = sVb + (st) * 9216 + (kr * QP + kc8 * 8) * 2; \
        CP_ASYNC(dk, ks); \
        CP_ASYNC(dk + 16 * QP * 2, ks + 16 * DD); \
        CP_ASYNC(dk + 32 * QP * 2, ks + 32 * DD); \
        CP_ASYNC(dk + 48 * QP * 2, ks + 48 * DD); \
        CP_ASYNC(dv, vs); \
        CP_ASYNC(dv + 16 * QP * 2, vs + 16 * DD); \
        CP_ASYNC(dv + 32 * QP * 2, vs + 32 * DD); \
        CP_ASYNC(dv + 48 * QP * 2, vs + 48 * DD); \
    } while (0)

    // Q tile: 128 rows (plain stores)
    {
        const uint4* src = (const uint4*)(Qg + (size_t)q0 * DD);
        #pragma unroll
        for (int i = tid; i < 1024; i += 128) {
            int r = i >> 3, cc = i & 7;
            *(uint4*)(sm + r * QP + cc * 8) = src[r * 8 + cc];
        }
    }

    KV_ISSUE(0, 0); CP_COMMIT();
    KV_ISSUE(1, 1); CP_COMMIT();
    __syncthreads();   // covers Q stores

    // Q a-frags: 2 row-tiles x 4 k-steps
    unsigned qa[2][4][4];
    #pragma unroll
    for (int rt = 0; rt < 2; rt++) {
        int qrow = wid * 32 + rt * 16 + (lane & 15);
        int cofs = (lane >> 4) * 8;
        #pragma unroll
        for (int s = 0; s < 4; s++)
            ldm_x4(qa[rt][s], sQb + (qrow * QP + s * 16 + cofs) * 2);
    }

    const unsigned kq = (((lane >> 4) * 8 + lr) * QP + ((lane >> 3) & 1) * 8) * 2;
    const unsigned vq = ((((lane >> 3) & 1) * 8 + lr) * QP + (lane >> 4) * 8) * 2;

    // adjacency row pointers: 2 row-tiles x 2 subrows
    const unsigned* mp00 = g_adjbits + ((size_t)bi * SS + q0 + wid * 32 + gid) * (SS / 32);
    const unsigned* mp01 = mp00 + 8  * (SS / 32);
    const unsigned* mp10 = mp00 + 16 * (SS / 32);
    const unsigned* mp11 = mp00 + 24 * (SS / 32);

    const unsigned onesb[2] = {0x3C003C00u, 0x3C003C00u};  // fp16 {1,1}

    float oc[2][8][4] = {};
    float cl[2][4] = {};

    int st = 0, sti = 2;
    for (int kt = 0; kt < 32; kt++) {
        if (kt == 31) CP_WAIT0(); else CP_WAIT1();
        __syncthreads();
        if (kt < 30) { KV_ISSUE(kt + 2, sti); CP_COMMIT(); }

        const unsigned kb_base = sKb + st * 9216;
        const unsigned vb_base = sVb + st * 9216;

        // S(log2-domain) = Qs . K^T, fp16 accumulator
        unsigned su[2][8][2] = {};
        #pragma unroll
        for (int s = 0; s < 4; s++) {
            #pragma unroll
            for (int ntp = 0; ntp < 4; ntp++) {
                unsigned kb[4];
                ldm_x4(kb, kb_base + kq + ntp * (16 * QP * 2) + s * 32);
                mma16816_h(su[0][2 * ntp],     qa[0][s], kb);
                mma16816_h(su[0][2 * ntp + 1], qa[0][s], kb + 2);
                mma16816_h(su[1][2 * ntp],     qa[1][s], kb);
                mma16816_h(su[1][2 * ntp + 1], qa[1][s], kb + 2);
            }
        }

        // masked 2^s epilogue: AND + ex2 directly on packed f16 d-frags
        unsigned ph[2][8][2];
        #pragma unroll
        for (int rt = 0; rt < 2; rt++) {
            const uint2 wv0 = *(const uint2*)((rt ? mp10 : mp00) + 2 * kt);
            const uint2 wv1 = *(const uint2*)((rt ? mp11 : mp01) + 2 * kt);
            #pragma unroll
            for (int nt = 0; nt < 8; nt++) {
                int cb = nt * 8 + 2 * tig;
                unsigned wa = (cb < 32) ? wv0.x : wv0.y;
                unsigned wb = (cb < 32) ? wv1.x : wv1.y;
                int sh = cb & 31;
                unsigned ba  = (wa >> sh) & 3u;
                unsigned bb2 = (wb >> sh) & 3u;
                unsigned mA = ((ba & 1u) ? 0x0000FFFFu : 0u) | ((ba & 2u) ? 0xFFFF0000u : 0u);
                unsigned mB = ((bb2 & 1u) ? 0x0000FFFFu : 0u) | ((bb2 & 2u) ? 0xFFFF0000u : 0u);
                ph[rt][nt][0] = h2_exp2u(su[rt][nt][0] & mA);
                ph[rt][nt][1] = h2_exp2u(su[rt][nt][1] & mB);
            }
        }

        // O += P . V ; l += P . 1  — each vb ldm feeds 4 MMAs
        #pragma unroll
        for (int s = 0; s < 4; s++) {
            unsigned pa0[4] = {ph[0][2 * s][0], ph[0][2 * s][1],
                               ph[0][2 * s + 1][0], ph[0][2 * s + 1][1]};
            unsigned pa1[4] = {ph[1][2 * s][0], ph[1][2 * s][1],
                               ph[1][2 * s + 1][0], ph[1][2 * s + 1][1]};
            mma16816(cl[0], pa0, onesb);
            mma16816(cl[1], pa1, onesb);
            #pragma unroll
            for (int ntp = 0; ntp < 4; ntp++) {
                unsigned vb[4];
                ldm_x4_t(vb, vb_base + vq + s * (16 * QP * 2) + ntp * 32);
                mma16816(oc[0][2 * ntp],     pa0, vb);
                mma16816(oc[0][2 * ntp + 1], pa0, vb + 2);
                mma16816(oc[1][2 * ntp],     pa1, vb);
                mma16816(oc[1][2 * ntp + 1], pa1, vb + 2);
            }
        }

        st = (st == 2) ? 0 : st + 1;
        sti = (sti == 2) ? 0 : sti + 1;
    }

    // store (no reduction: each warp owns its 32 rows completely)
    #pragma unroll
    for (int rt = 0; rt < 2; rt++) {
        const float inv0 = 1.0f / cl[rt][0], inv1 = 1.0f / cl[rt][2];
        const int r = q0 + wid * 32 + rt * 16 + gid;
        __half* o0 = g_oh + ((size_t)bi * SS + r) * EE + hi * 64;
        __half* o1 = o0 + 8 * EE;
        #pragma unroll
        for (int nt = 0; nt < 8; nt++) {
            int cc = nt * 8 + 2 * tig;
            *(__half2*)(o0 + cc) = __floats2half2_rn(oc[rt][nt][0] * inv0,
                                                     oc[rt][nt][1] * inv0);
            *(__half2*)(o1 + cc) = __floats2half2_rn(oc[rt][nt][2] * inv1,
                                                     oc[rt][nt][3] * inv1);
        }
    }
}

// ---------------------------------------------------------------------------
// Kernel E: output projection, HMMA (R9-R14 version, measured ~21us).
// ---------------------------------------------------------------------------
__global__ __launch_bounds__(128, 4) void out_hmma_kernel(
    const float* __restrict__ bias, float* __restrict__ out)
{
    extern __shared__ __align__(16) __half sm[];
    const unsigned sAb = smem_u32(sm);            // 3 stages x 9216
    const unsigned sBb = sAb + 27648;             // 3 stages x 9216

    const int tid = threadIdx.x;
    const int wid = tid >> 5, lane = tid & 31;
    const int gid = lane >> 2, tig = lane & 3, lr = lane & 7;
    const int m0 = blockIdx.y * 64, n0 = blockIdx.x * 64;

    const __half* A = g_oh;    // [8192,512]
    const __half* B = g_woh;   // [512,512]
    const int ar = tid >> 3, ac = tid & 7;        // 16 rows per pass

    #define OUT_ISSUE(kc, st) do { \
        unsigned da = sAb + (st) * 9216; \
        const __half* as = A + (size_t)(m0 + ar) * 512 + (kc) * 64 + ac * 8; \
        CP_ASYNC(da + (ar * QP + ac * 8) * 2, as); \
        CP_ASYNC(da + ((ar + 16) * QP + ac * 8) * 2, as + 16 * 512); \
        CP_ASYNC(da + ((ar + 32) * QP + ac * 8) * 2, as + 32 * 512); \
        CP_ASYNC(da + ((ar + 48) * QP + ac * 8) * 2, as + 48 * 512); \
        unsigned db = sBb + (st) * 9216; \
        const __half* bs = B + (size_t)(n0 + ar) * 512 + (kc) * 64 + ac * 8; \
        CP_ASYNC(db + (ar * QP + ac * 8) * 2, bs); \
        CP_ASYNC(db + ((ar + 16) * QP + ac * 8) * 2, bs + 16 * 512); \
        CP_ASYNC(db + ((ar + 32) * QP + ac * 8) * 2, bs + 32 * 512); \
        CP_ASYNC(db + ((ar + 48) * QP + ac * 8) * 2, bs + 48 * 512); \
    } while (0)

    const unsigned aq = ((wid * 16 + (lane & 15)) * QP + (lane >> 4) * 8) * 2;
    const unsigned bq = (((lane >> 4) * 8 + lr) * QP + ((lane >> 3) & 1) * 8) * 2;

    float c[8][4] = {};

    OUT_ISSUE(0, 0); CP_COMMIT();
    OUT_ISSUE(1, 1); CP_COMMIT();

    int st = 0, sti = 2;
    for (int kc = 0; kc < 8; kc++) {
        if (kc == 7) CP_WAIT0(); else CP_WAIT1();
        __syncthreads();
        if (kc < 6) { OUT_ISSUE(kc + 2, sti); CP_COMMIT(); }
        const unsigned ab = sAb + st * 9216;
        const unsigned bb = sBb + st * 9216;
        #pragma unroll
        for (int s = 0; s < 4; s++) {
            unsigned af[4];
            ldm_x4(af, ab + aq + s * 32);
            #pragma unroll
            for (int ntp = 0; ntp < 4; ntp++) {
                unsigned bf[4];
                ldm_x4(bf, bb + bq + ntp * (16 * QP * 2) + s * 32);
                mma16816(c[2 * ntp],     af, bf);
                mma16816(c[2 * ntp + 1], af, bf + 2);
            }
        }
        st = (st == 2) ? 0 : st + 1;
        sti = (sti == 2) ? 0 : sti + 1;
    }

    const int r0 = m0 + wid * 16 + gid;
    float* o0 = out + (size_t)r0 * EE;
    float* o1 = o0 + 8 * EE;
    #pragma unroll
    for (int nt = 0; nt < 8; nt++) {
        int col = n0 + nt * 8 + 2 * tig;
        float b0 = bias[col], b1 = bias[col + 1];
        *(float2*)(o0 + col) = make_float2(c[nt][0] + b0, c[nt][1] + b1);
        *(float2*)(o1 + col) = make_float2(c[nt][2] + b0, c[nt][3] + b1);
    }
}

// ---------------------------------------------------------------------------
// Launch
// ---------------------------------------------------------------------------
extern "C" void kernel_launch(void* const* d_in, const int* in_sizes, int n_in,
                              void* d_out, int out_size)
{
    const float* x      = (const float*)d_in[0];
    const float* adj    = (const float*)d_in[1];
    const float* Wqkv_w = (const float*)d_in[2];
    const float* Wqkv_b = (const float*)d_in[3];
    const float* out_w  = (const float*)d_in[4];
    const float* out_b  = (const float*)d_in[5];
    float* out = (float*)d_out;

    cudaFuncSetAttribute(qkvpack_kernel,  cudaFuncAttributeMaxDynamicSharedMemorySize, 110592);
    cudaFuncSetAttribute(attn_kernel,     cudaFuncAttributeMaxDynamicSharedMemorySize, 73728);
    cudaFuncSetAttribute(out_hmma_kernel, cudaFuncAttributeMaxDynamicSharedMemorySize, 55296);

    conv_kernel<<<2432, 256>>>(x, Wqkv_w);
    qkvpack_kernel<<<2176, 256, 110592>>>(Wqkv_b, adj, out_w);
    attn_kernel<<<dim3(SS / 128, HH, BB), 128, 73728>>>();
    out_hmma_kernel<<<dim3(8, 128), 128, 55296>>>(out_b, out);
}